// round 5
// baseline (speedup 1.0000x reference)
#include <cuda_runtime.h>
#include <cuda_bf16.h>
#include <cstdint>
#include <cstddef>

// ---------------- problem constants ----------------
#define Bb   4
#define Np   16384
#define Cf   128
#define Mq   1024
#define Kq   32
#define NNc  131072            // Bb*Mq*Kq  (GEMM column count)
#define R2c  0.16f
#define EPSv 1e-5f
#define KCP1 192               // layer1 K padded (131 -> 192)
#define KCP2 128
#define NCTA 1024              // N-blocks per layer (NNc/128)

// ---------------- scratch (device globals) ----------------
__device__ int   g_idx[NNc];
__device__ __align__(16) unsigned short g_Xhi[(size_t)NNc * KCP1];   // 50 MB
__device__ __align__(16) unsigned short g_Xlo[(size_t)NNc * KCP1];
__device__ __align__(16) unsigned short g_Whi[128*KCP1 + 128*128 + 256*128];
__device__ __align__(16) unsigned short g_Wlo[128*KCP1 + 128*128 + 256*128];
__device__ float g_featT[(size_t)Bb * Np * Cf];                      // 32 MB
__device__ float g_Y1[(size_t)128 * NNc];                            // 64 MB
__device__ float g_Y2[(size_t)128 * NNc];                            // 64 MB
__device__ float g_Y3[(size_t)256 * NNc];                            // 128 MB
__device__ float g_ps[256 * NCTA];
__device__ float g_pq[256 * NCTA];
__device__ float g_scale[256];
__device__ float g_shift[256];

// ---------------- helpers ----------------
__device__ __forceinline__ uint32_t smem_u32(const void* p) {
    uint32_t a;
    asm("{ .reg .u64 t; cvta.to.shared.u64 t, %1; cvt.u32.u64 %0, t; }" : "=r"(a) : "l"(p));
    return a;
}
__device__ __forceinline__ void bf16_split(float x, unsigned short& h, unsigned short& l) {
    __nv_bfloat16 bh = __float2bfloat16_rn(x);
    float r = x - __bfloat162float(bh);
    __nv_bfloat16 bl = __float2bfloat16_rn(r);
    h = __bfloat16_as_ushort(bh);
    l = __bfloat16_as_ushort(bl);
}
__device__ __forceinline__ unsigned long long pack4(unsigned short a, unsigned short b,
                                                    unsigned short c, unsigned short d) {
    return (unsigned long long)a | ((unsigned long long)b << 16) |
           ((unsigned long long)c << 32) | ((unsigned long long)d << 48);
}

#define LDSM_X4(d0,d1,d2,d3,a) \
    asm volatile("ldmatrix.sync.aligned.m8n8.x4.shared.b16 {%0,%1,%2,%3},[%4];" \
                 : "=r"(d0),"=r"(d1),"=r"(d2),"=r"(d3) : "r"(a))
#define LDSM_X2(d0,d1,a) \
    asm volatile("ldmatrix.sync.aligned.m8n8.x2.shared.b16 {%0,%1},[%2];" \
                 : "=r"(d0),"=r"(d1) : "r"(a))
#define MMA16816(c, a, b) \
    asm volatile("mma.sync.aligned.m16n8k16.row.col.f32.bf16.bf16.f32 " \
                 "{%0,%1,%2,%3},{%4,%5,%6,%7},{%8,%9},{%0,%1,%2,%3};" \
                 : "+f"((c)[0]),"+f"((c)[1]),"+f"((c)[2]),"+f"((c)[3]) \
                 : "r"((a)[0]),"r"((a)[1]),"r"((a)[2]),"r"((a)[3]), \
                   "r"((b)[0]),"r"((b)[1]))

// ---------------- kernel: gather new_xyz ----------------
__global__ void k_newxyz(const float* __restrict__ pxyz, const int* __restrict__ ind,
                         float* __restrict__ out)
{
    int i = blockIdx.x * blockDim.x + threadIdx.x;
    if (i >= Bb * Mq) return;
    int b = i >> 10;
    int n = ind[i];
    const float* p = pxyz + ((size_t)b * Np + n) * 3;
    out[i * 3 + 0] = p[0];
    out[i * 3 + 1] = p[1];
    out[i * 3 + 2] = p[2];
}

// ---------------- kernel: ball query (warp per query) ----------------
__global__ void k_ballquery(const float* __restrict__ pxyz, const float* __restrict__ nxyz)
{
    int gtid = blockIdx.x * blockDim.x + threadIdx.x;
    int q    = gtid >> 5;
    int lane = gtid & 31;
    int b    = q >> 10;

    float nx = nxyz[q * 3 + 0], ny = nxyz[q * 3 + 1], nz = nxyz[q * 3 + 2];
    const float* px = pxyz + (size_t)b * Np * 3;

    int cnt = 0, first = 0;
    for (int n0 = 0; n0 < Np; n0 += 32) {
        int n = n0 + lane;
        float dx = px[n * 3 + 0] - nx, dy = px[n * 3 + 1] - ny, dz = px[n * 3 + 2] - nz;
        float d2 = __fadd_rn(__fadd_rn(__fmul_rn(dx, dx), __fmul_rn(dy, dy)), __fmul_rn(dz, dz));
        bool within = d2 < R2c;
        unsigned bal = __ballot_sync(0xffffffffu, within);
        if (bal) {
            if (cnt == 0) first = n0 + __ffs(bal) - 1;
            int pre = __popc(bal & ((1u << lane) - 1u));
            if (within && (cnt + pre) < Kq) g_idx[q * Kq + cnt + pre] = n;
            cnt += __popc(bal);
            if (cnt >= Kq) break;
        }
    }
    cnt = min(cnt, Kq);
    if (lane >= cnt) g_idx[q * Kq + lane] = first;
}

// ---------------- kernel: transpose features -> featT[b][n][c] ----------------
__global__ void k_transpose(const float* __restrict__ f, float* __restrict__ ft)
{
    __shared__ float t[32][33];
    int b  = blockIdx.z;
    int n0 = blockIdx.x << 5, c0 = blockIdx.y << 5;
    int tx = threadIdx.x, ty = threadIdx.y;       // 32 x 8
#pragma unroll
    for (int i = 0; i < 32; i += 8)
        t[ty + i][tx] = f[((size_t)b * Cf + c0 + ty + i) * Np + n0 + tx];
    __syncthreads();
#pragma unroll
    for (int i = 0; i < 32; i += 8)
        ft[((size_t)b * Np + n0 + ty + i) * Cf + c0 + tx] = t[tx][ty + i];
}

// ---------------- kernel: pack weights -> bf16 hi/lo (layer1 permutes channels) ----------------
__global__ void k_packW(const float* __restrict__ W, unsigned short* __restrict__ Whi,
                        unsigned short* __restrict__ Wlo, int KC, int KCp, int perm)
{
    int o = blockIdx.x, c = threadIdx.x;
    if (c >= KCp) return;
    float v = 0.f;
    if (perm) {
        // packed channel order: 0..127 = feat (orig 3..130), 128..130 = xyz (orig 0..2)
        int oc = (c < 128) ? (c + 3) : ((c < 131) ? (c - 128) : -1);
        if (oc >= 0) v = W[o * 131 + oc];
    } else if (c < KC) {
        v = W[o * KC + c];
    }
    unsigned short h, l;
    bf16_split(v, h, l);
    Whi[o * KCp + c] = h;
    Wlo[o * KCp + c] = l;
}

// ---------------- kernel: pack layer-1 input (gather + concat + split), warp per col ----------------
__global__ void k_pack1(const float* __restrict__ pxyz, const float* __restrict__ nxyz)
{
    int col  = (blockIdx.x * blockDim.x + threadIdx.x) >> 5;
    int lane = threadIdx.x & 31;
    if (col >= NNc) return;
    int idx = g_idx[col];
    int b   = col >> 15;

    const float4* fr = (const float4*)&g_featT[((size_t)b * Np + idx) * Cf];
    float4 v = fr[lane];
    unsigned short h0,l0,h1,l1,h2,l2,h3,l3;
    bf16_split(v.x, h0, l0); bf16_split(v.y, h1, l1);
    bf16_split(v.z, h2, l2); bf16_split(v.w, h3, l3);
    size_t xb = (size_t)col * KCP1;
    *(unsigned long long*)&g_Xhi[xb + lane * 4] = pack4(h0, h1, h2, h3);
    *(unsigned long long*)&g_Xlo[xb + lane * 4] = pack4(l0, l1, l2, l3);

    if (lane < 3) {
        int q = col >> 5;
        float x = pxyz[((size_t)b * Np + idx) * 3 + lane] - nxyz[q * 3 + lane];
        unsigned short h, l;
        bf16_split(x, h, l);
        g_Xhi[xb + 128 + lane] = h;
        g_Xlo[xb + 128 + lane] = l;
    }
    if (lane < 31) { g_Xhi[xb + 131 + lane] = 0; g_Xlo[xb + 131 + lane] = 0; }
    if (lane < 30) { g_Xhi[xb + 162 + lane] = 0; g_Xlo[xb + 162 + lane] = 0; }
}

// ---------------- kernel: BN+ReLU + transpose-pack Y -> X bf16 hi/lo ----------------
__global__ void k_packbn(const float* __restrict__ Y)
{
    int n = blockIdx.x * 256 + threadIdx.x;      // column
    size_t xb = (size_t)n * KCP2;
#pragma unroll 4
    for (int c = 0; c < 128; c += 4) {
        unsigned short h[4], l[4];
#pragma unroll
        for (int j = 0; j < 4; j++) {
            float y = Y[(size_t)(c + j) * NNc + n];
            float v = fmaxf(fmaf(g_scale[c + j], y, g_shift[c + j]), 0.f);
            bf16_split(v, h[j], l[j]);
        }
        *(unsigned long long*)&g_Xhi[xb + c] = pack4(h[0], h[1], h[2], h[3]);
        *(unsigned long long*)&g_Xlo[xb + c] = pack4(l[0], l[1], l[2], l[3]);
    }
}

// ---------------- kernel: HMMA GEMM via mma.sync (bf16 3-term split) ----------------
// Y[o][n] = sum_c W[o][c]*X[n][c] + bias[o]; emits per-CTA channel partial stats.
// CTA: 128(M) x 128(N), K-chunk 32. 8 warps in 2(M) x 4(N); warp tile 64x32.
#define SSTR 40   // smem K-stride in halves (80B, conflict-free for ldmatrix)
__global__ void __launch_bounds__(256, 1) k_gemm_mma(
    const unsigned short* __restrict__ Whi, const unsigned short* __restrict__ Wlo,
    const float* __restrict__ bias, int KCp, int kchunks, float* __restrict__ Y)
{
    __shared__ __align__(16) unsigned short sAhi[128 * SSTR], sAlo[128 * SSTR];
    __shared__ __align__(16) unsigned short sBhi[128 * SSTR], sBlo[128 * SSTR];
    __shared__ float s_sum[128], s_sq[128];

    const int tid  = threadIdx.x;
    const int wid  = tid >> 5, lane = tid & 31;
    const int n0   = blockIdx.x << 7;
    const int o0   = blockIdx.y << 7;
    const int wm   = wid >> 2;          // 0..1 -> m base wm*64
    const int wn   = wid & 3;           // 0..3 -> n base wn*32

    if (tid < 128) { s_sum[tid] = 0.f; s_sq[tid] = 0.f; }

    // global<->smem staging coords: thread covers row lr, halves [lk, lk+16)
    const int lr    = tid >> 1;
    const int lk    = (tid & 1) << 4;
    const int s_off = lr * SSTR + lk;

    // ldmatrix source addresses (bytes)
    const uint32_t bAhi = smem_u32(sAhi), bAlo = smem_u32(sAlo);
    const uint32_t bBhi = smem_u32(sBhi), bBlo = smem_u32(sBlo);
    const uint32_t rowA = ((wm * 64 + (lane & 15)) * SSTR + (lane >> 4) * 8) * 2;
    const uint32_t rowB = ((wn * 32 + (lane & 7)) * SSTR + ((lane >> 3) & 1) * 8) * 2;

    float acc[4][4][4];
#pragma unroll
    for (int mt = 0; mt < 4; mt++)
#pragma unroll
        for (int nt = 0; nt < 4; nt++)
#pragma unroll
            for (int r = 0; r < 4; r++) acc[mt][nt][r] = 0.f;

    // prefetch B chunk 0
    uint4 pbh0, pbh1, pbl0, pbl1;
    {
        size_t g = (size_t)(n0 + lr) * KCp + lk;
        pbh0 = *(const uint4*)&g_Xhi[g]; pbh1 = *(const uint4*)&g_Xhi[g + 8];
        pbl0 = *(const uint4*)&g_Xlo[g]; pbl1 = *(const uint4*)&g_Xlo[g + 8];
    }

    for (int kt = 0; kt < kchunks; kt++) {
        __syncthreads();
        // stage B from prefetch regs
        *(uint4*)&sBhi[s_off]     = pbh0;
        *(uint4*)&sBhi[s_off + 8] = pbh1;
        *(uint4*)&sBlo[s_off]     = pbl0;
        *(uint4*)&sBlo[s_off + 8] = pbl1;
        // stage A direct (L2-resident)
        {
            size_t g = (size_t)(o0 + lr) * KCp + kt * 32 + lk;
            *(uint4*)&sAhi[s_off]     = *(const uint4*)&Whi[g];
            *(uint4*)&sAhi[s_off + 8] = *(const uint4*)&Whi[g + 8];
            *(uint4*)&sAlo[s_off]     = *(const uint4*)&Wlo[g];
            *(uint4*)&sAlo[s_off + 8] = *(const uint4*)&Wlo[g + 8];
        }
        __syncthreads();
        if (kt + 1 < kchunks) {       // overlap next-chunk DRAM loads with MMA
            size_t g = (size_t)(n0 + lr) * KCp + (kt + 1) * 32 + lk;
            pbh0 = *(const uint4*)&g_Xhi[g]; pbh1 = *(const uint4*)&g_Xhi[g + 8];
            pbl0 = *(const uint4*)&g_Xlo[g]; pbl1 = *(const uint4*)&g_Xlo[g + 8];
        }

#pragma unroll
        for (int ks = 0; ks < 2; ks++) {
            uint32_t ah[4][4], al[4][4], bh[4][2], bl[4][2];
#pragma unroll
            for (int mt = 0; mt < 4; mt++) {
                uint32_t off = rowA + mt * (16 * SSTR * 2) + ks * 32;
                LDSM_X4(ah[mt][0], ah[mt][1], ah[mt][2], ah[mt][3], bAhi + off);
                LDSM_X4(al[mt][0], al[mt][1], al[mt][2], al[mt][3], bAlo + off);
            }
#pragma unroll
            for (int nt = 0; nt < 4; nt++) {
                uint32_t off = rowB + nt * (8 * SSTR * 2) + ks * 32;
                LDSM_X2(bh[nt][0], bh[nt][1], bBhi + off);
                LDSM_X2(bl[nt][0], bl[nt][1], bBlo + off);
            }
#pragma unroll
            for (int mt = 0; mt < 4; mt++)
#pragma unroll
                for (int nt = 0; nt < 4; nt++) {
                    MMA16816(acc[mt][nt], ah[mt], bh[nt]);   // hi*hi
                    MMA16816(acc[mt][nt], ah[mt], bl[nt]);   // hi*lo
                    MMA16816(acc[mt][nt], al[mt], bh[nt]);   // lo*hi
                }
        }
    }

    // ---- epilogue: bias add, store Y, per-channel partial stats ----
    const int qid = lane >> 2;          // row within 8
    const int qt  = lane & 3;           // column pair selector
#pragma unroll
    for (int mt = 0; mt < 4; mt++) {
        int m1 = wm * 64 + mt * 16 + qid;
        int m2 = m1 + 8;
        float bb1 = bias[o0 + m1], bb2 = bias[o0 + m2];
        float s1 = 0.f, q1 = 0.f, s2 = 0.f, q2 = 0.f;
#pragma unroll
        for (int nt = 0; nt < 4; nt++) {
            int n = n0 + wn * 32 + nt * 8 + qt * 2;
            float v0 = acc[mt][nt][0] + bb1, v1 = acc[mt][nt][1] + bb1;
            float v2 = acc[mt][nt][2] + bb2, v3 = acc[mt][nt][3] + bb2;
            *(float2*)&Y[(size_t)(o0 + m1) * NNc + n] = make_float2(v0, v1);
            *(float2*)&Y[(size_t)(o0 + m2) * NNc + n] = make_float2(v2, v3);
            s1 += v0 + v1; q1 += v0 * v0 + v1 * v1;
            s2 += v2 + v3; q2 += v2 * v2 + v3 * v3;
        }
        // reduce across the 4 lanes of the quad
        s1 += __shfl_xor_sync(0xffffffffu, s1, 1); s1 += __shfl_xor_sync(0xffffffffu, s1, 2);
        q1 += __shfl_xor_sync(0xffffffffu, q1, 1); q1 += __shfl_xor_sync(0xffffffffu, q1, 2);
        s2 += __shfl_xor_sync(0xffffffffu, s2, 1); s2 += __shfl_xor_sync(0xffffffffu, s2, 2);
        q2 += __shfl_xor_sync(0xffffffffu, q2, 1); q2 += __shfl_xor_sync(0xffffffffu, q2, 2);
        if (qt == 0) {
            atomicAdd(&s_sum[m1], s1); atomicAdd(&s_sq[m1], q1);
            atomicAdd(&s_sum[m2], s2); atomicAdd(&s_sq[m2], q2);
        }
    }
    __syncthreads();
    if (tid < 128) {
        g_ps[(size_t)(o0 + tid) * NCTA + blockIdx.x] = s_sum[tid];
        g_pq[(size_t)(o0 + tid) * NCTA + blockIdx.x] = s_sq[tid];
    }
}

// ---------------- kernel: reduce partials -> BN scale/shift ----------------
__global__ void k_reduce(const float* __restrict__ gam, const float* __restrict__ bet)
{
    __shared__ float ss[256], sq[256];
    int c = blockIdx.x, t = threadIdx.x;
    float s = g_ps[(size_t)c * NCTA + t]       + g_ps[(size_t)c * NCTA + 256 + t]
            + g_ps[(size_t)c * NCTA + 512 + t] + g_ps[(size_t)c * NCTA + 768 + t];
    float q = g_pq[(size_t)c * NCTA + t]       + g_pq[(size_t)c * NCTA + 256 + t]
            + g_pq[(size_t)c * NCTA + 512 + t] + g_pq[(size_t)c * NCTA + 768 + t];
    ss[t] = s; sq[t] = q;
    __syncthreads();
    for (int st = 128; st > 0; st >>= 1) {
        if (t < st) { ss[t] += ss[t + st]; sq[t] += sq[t + st]; }
        __syncthreads();
    }
    if (t == 0) {
        float mean = ss[0] * (1.f / NNc);
        float var  = sq[0] * (1.f / NNc) - mean * mean;
        float rs   = rsqrtf(var + EPSv);
        float sc   = gam[c] * rs;
        g_scale[c] = sc;
        g_shift[c] = fmaf(-mean, sc, bet[c]);
    }
}

// ---------------- kernel: BN3 + ReLU + max over K ----------------
__global__ void k_final(const float* __restrict__ Y3, float* __restrict__ outf)
{
    int i = blockIdx.x * blockDim.x + threadIdx.x;
    int m = i & (Mq - 1);
    int o = (i >> 10) & 255;
    int b = i >> 18;
    size_t base = (size_t)o * NNc + (((size_t)b << 10) + m) * Kq;
    const float4* p = (const float4*)(Y3 + base);
    float sc = g_scale[o], sh = g_shift[o];
    float mx = 0.f;
#pragma unroll
    for (int t = 0; t < 8; t++) {
        float4 v = p[t];
        mx = fmaxf(mx, fmaxf(fmaf(sc, v.x, sh), 0.f));
        mx = fmaxf(mx, fmaxf(fmaf(sc, v.y, sh), 0.f));
        mx = fmaxf(mx, fmaxf(fmaf(sc, v.z, sh), 0.f));
        mx = fmaxf(mx, fmaxf(fmaf(sc, v.w, sh), 0.f));
    }
    outf[((size_t)b * 256 + o) * Mq + m] = mx;
}

// ---------------- host launcher ----------------
extern "C" void kernel_launch(void* const* d_in, const int* in_sizes, int n_in,
                              void* d_out, int out_size)
{
    const float* pxyz = (const float*)d_in[0];
    const float* feat = (const float*)d_in[1];
    const int*   ind  = (const int*)d_in[2];
    const float* w1 = (const float*)d_in[3];  const float* b1 = (const float*)d_in[4];
    const float* g1 = (const float*)d_in[5];  const float* be1 = (const float*)d_in[6];
    const float* w2 = (const float*)d_in[7];  const float* b2 = (const float*)d_in[8];
    const float* g2 = (const float*)d_in[9];  const float* be2 = (const float*)d_in[10];
    const float* w3 = (const float*)d_in[11]; const float* b3 = (const float*)d_in[12];
    const float* g3 = (const float*)d_in[13]; const float* be3 = (const float*)d_in[14];

    float* out  = (float*)d_out;
    float* nxyz = out;
    float* fout = out + Bb * Mq * 3;

    float *pY1, *pY2, *pY3, *pFT;
    unsigned short *pWhi, *pWlo;
    cudaGetSymbolAddress((void**)&pY1, g_Y1);
    cudaGetSymbolAddress((void**)&pY2, g_Y2);
    cudaGetSymbolAddress((void**)&pY3, g_Y3);
    cudaGetSymbolAddress((void**)&pFT, g_featT);
    cudaGetSymbolAddress((void**)&pWhi, g_Whi);
    cudaGetSymbolAddress((void**)&pWlo, g_Wlo);

    const int W2_OFF = 128 * KCP1;
    const int W3_OFF = 128 * KCP1 + 128 * 128;

    k_newxyz<<<(Bb * Mq + 255) / 256, 256>>>(pxyz, ind, nxyz);
    k_ballquery<<<(Bb * Mq * 32) / 256, 256>>>(pxyz, nxyz);
    k_transpose<<<dim3(Np / 32, Cf / 32, Bb), dim3(32, 8)>>>(feat, pFT);

    k_packW<<<128, KCP1>>>(w1, pWhi, pWlo, 131, KCP1, 1);
    k_packW<<<128, 128>>>(w2, pWhi + W2_OFF, pWlo + W2_OFF, 128, 128, 0);
    k_packW<<<256, 128>>>(w3, pWhi + W3_OFF, pWlo + W3_OFF, 128, 128, 0);

    // layer 1  (K = 192 -> 6 chunks of 32)
    k_pack1<<<NNc / 8, 256>>>(pxyz, nxyz);
    k_gemm_mma<<<dim3(NCTA, 1), 256>>>(pWhi, pWlo, b1, KCP1, 6, pY1);
    k_reduce<<<128, 256>>>(g1, be1);

    // layer 2  (K = 128 -> 4 chunks)
    k_packbn<<<512, 256>>>(pY1);
    k_gemm_mma<<<dim3(NCTA, 1), 256>>>(pWhi + W2_OFF, pWlo + W2_OFF, b2, KCP2, 4, pY2);
    k_reduce<<<128, 256>>>(g2, be2);

    // layer 3  (256 out channels -> 2 M-blocks)
    k_packbn<<<512, 256>>>(pY2);
    k_gemm_mma<<<dim3(NCTA, 2), 256>>>(pWhi + W3_OFF, pWlo + W3_OFF, b3, KCP2, 4, pY3);
    k_reduce<<<256, 256>>>(g3, be3);

    k_final<<<(Bb * 256 * Mq) / 256, 256>>>(pY3, fout);
}

// round 6
// speedup vs baseline: 2.0182x; 2.0182x over previous
#include <cuda_runtime.h>
#include <cuda_bf16.h>
#include <cstdint>
#include <cstddef>

// ---------------- problem constants ----------------
#define Bb   4
#define Np   16384
#define Cf   128
#define Mq   1024
#define Kq   32
#define NNc  131072            // Bb*Mq*Kq (GEMM column count)
#define R2c  0.16f
#define EPSv 1e-5f
#define KCP1 160               // layer1 K padded (131 -> 160 = 5 chunks of 32)
#define KCP2 128
#define NCTA 1024

// ---------------- scratch (device globals) ----------------
__device__ int   g_idx[NNc];
__device__ float g_Wt[KCP1*128 + 128*128 + 128*256];   // tf32-rounded, [c][o]
__device__ float g_featT[(size_t)Bb * Np * Cf];        // 32 MB
__device__ float g_Y1[(size_t)128 * NNc];              // 64 MB
__device__ float g_Y2[(size_t)128 * NNc];              // 64 MB
__device__ float g_Y3[(size_t)256 * NNc];              // 128 MB
__device__ float g_ps[256 * NCTA];
__device__ float g_pq[256 * NCTA];
__device__ float g_scale[256];
__device__ float g_shift[256];

// ---------------- helpers ----------------
__device__ __forceinline__ uint32_t smem_u32(const void* p) {
    uint32_t a;
    asm("{ .reg .u64 t; cvta.to.shared.u64 t, %1; cvt.u32.u64 %0, t; }" : "=r"(a) : "l"(p));
    return a;
}
__device__ __forceinline__ uint32_t to_tf32(float x) {
    uint32_t u;
    asm("cvt.rna.tf32.f32 %0, %1;" : "=r"(u) : "f"(x));
    return u;
}
#define CPASYNC16(dst, src) \
    asm volatile("cp.async.ca.shared.global [%0],[%1],16;" :: "r"(dst), "l"(src))
#define MMA1688(c, a, b) \
    asm volatile("mma.sync.aligned.m16n8k8.row.col.f32.tf32.tf32.f32 " \
                 "{%0,%1,%2,%3},{%4,%5,%6,%7},{%8,%9},{%0,%1,%2,%3};" \
                 : "+f"((c)[0]),"+f"((c)[1]),"+f"((c)[2]),"+f"((c)[3]) \
                 : "r"((a)[0]),"r"((a)[1]),"r"((a)[2]),"r"((a)[3]), \
                   "r"((b)[0]),"r"((b)[1]))

// ---------------- kernel: gather new_xyz ----------------
__global__ void k_newxyz(const float* __restrict__ pxyz, const int* __restrict__ ind,
                         float* __restrict__ out)
{
    int i = blockIdx.x * blockDim.x + threadIdx.x;
    if (i >= Bb * Mq) return;
    int b = i >> 10;
    int n = ind[i];
    const float* p = pxyz + ((size_t)b * Np + n) * 3;
    out[i * 3 + 0] = p[0];
    out[i * 3 + 1] = p[1];
    out[i * 3 + 2] = p[2];
}

// ---------------- kernel: ball query (warp per query) ----------------
__global__ void k_ballquery(const float* __restrict__ pxyz, const float* __restrict__ nxyz)
{
    int gtid = blockIdx.x * blockDim.x + threadIdx.x;
    int q    = gtid >> 5;
    int lane = gtid & 31;
    int b    = q >> 10;

    float nx = nxyz[q * 3 + 0], ny = nxyz[q * 3 + 1], nz = nxyz[q * 3 + 2];
    const float* px = pxyz + (size_t)b * Np * 3;

    int cnt = 0, first = 0;
    for (int n0 = 0; n0 < Np; n0 += 32) {
        int n = n0 + lane;
        float dx = px[n * 3 + 0] - nx, dy = px[n * 3 + 1] - ny, dz = px[n * 3 + 2] - nz;
        float d2 = __fadd_rn(__fadd_rn(__fmul_rn(dx, dx), __fmul_rn(dy, dy)), __fmul_rn(dz, dz));
        bool within = d2 < R2c;
        unsigned bal = __ballot_sync(0xffffffffu, within);
        if (bal) {
            if (cnt == 0) first = n0 + __ffs(bal) - 1;
            int pre = __popc(bal & ((1u << lane) - 1u));
            if (within && (cnt + pre) < Kq) g_idx[q * Kq + cnt + pre] = n;
            cnt += __popc(bal);
            if (cnt >= Kq) break;
        }
    }
    cnt = min(cnt, Kq);
    if (lane >= cnt) g_idx[q * Kq + lane] = first;
}

// ---------------- kernel: transpose features -> featT[b][n][c] ----------------
__global__ void k_transpose(const float* __restrict__ f, float* __restrict__ ft)
{
    __shared__ float t[32][33];
    int b  = blockIdx.z;
    int n0 = blockIdx.x << 5, c0 = blockIdx.y << 5;
    int tx = threadIdx.x, ty = threadIdx.y;       // 32 x 8
#pragma unroll
    for (int i = 0; i < 32; i += 8)
        t[ty + i][tx] = f[((size_t)b * Cf + c0 + ty + i) * Np + n0 + tx];
    __syncthreads();
#pragma unroll
    for (int i = 0; i < 32; i += 8)
        ft[((size_t)b * Np + n0 + ty + i) * Cf + c0 + tx] = t[tx][ty + i];
}

// ---------------- kernel: pack weights -> tf32 transposed Wt[c][o] ----------------
__global__ void k_packWt(const float* __restrict__ W, float* __restrict__ Wt,
                         int KC, int Osz, int perm)
{
    int c = blockIdx.x, o = threadIdx.x;
    float v = 0.f;
    if (perm) {
        // packed channel order: 0..127 = feat (orig 3..130), 128..130 = xyz (orig 0..2)
        int oc = (c < 128) ? (c + 3) : ((c < 131) ? (c - 128) : -1);
        if (oc >= 0) v = W[o * 131 + oc];
    } else if (c < KC) {
        v = W[o * KC + c];
    }
    uint32_t u = to_tf32(v);
    Wt[c * Osz + o] = __uint_as_float(u);
}

// ---------------- fused tf32 GEMM ----------------
// Y[o][n] = sum_c W[o][c] * X[n][c] + bias[o]; per-CTA channel partial stats.
// CTA tile 128(M) x 128(N), K-chunk 32; 8 warps 2(M)x4(N), warp tile 64x32.
// MODE 0: B generated by gather/concat on the fly (layer 1)
// MODE 1: B = relu(scale*Yprev + shift) (layers 2/3)
#define SBS 136   // smem row stride in 4B elems (conflict-free: 136%32==8)
template <int MODE>
__global__ void __launch_bounds__(256, 2) k_gemm_tf32(
    const float* __restrict__ Wt, const float* __restrict__ bias,
    int kchunks, int Osz,
    const float* __restrict__ Bsrc,
    const float* __restrict__ pxyz, const float* __restrict__ nxyz,
    float* __restrict__ Y)
{
    __shared__ uint32_t sA[32 * SBS];
    __shared__ uint32_t sB[32 * SBS];
    __shared__ float s_sum[128], s_sq[128];

    const int tid  = threadIdx.x;
    const int wid  = tid >> 5, lane = tid & 31;
    const int n0   = blockIdx.x << 7;
    const int o0   = blockIdx.y << 7;
    const int wm   = wid >> 2;
    const int wn   = wid & 3;

    if (tid < 128) { s_sum[tid] = 0.f; s_sq[tid] = 0.f; }

    const uint32_t sAb = smem_u32(sA);

    float acc[4][4][4];
#pragma unroll
    for (int mt = 0; mt < 4; mt++)
#pragma unroll
        for (int nt = 0; nt < 4; nt++)
#pragma unroll
            for (int r = 0; r < 4; r++) acc[mt][nt][r] = 0.f;

    for (int kt = 0; kt < kchunks; kt++) {
        __syncthreads();
        // ---- A: straight cp.async from pre-packed Wt (tf32 bits) ----
#pragma unroll
        for (int s = 0; s < 4; s++) {
            int idx = tid + (s << 8);
            int c = idx >> 5, seg = idx & 31;
            const float* src = Wt + (size_t)(kt * 32 + c) * Osz + o0 + seg * 4;
            uint32_t dst = sAb + (c * SBS + seg * 4) * 4;
            CPASYNC16(dst, src);
        }
        // ---- B: transform in registers, store tf32 to smem ----
        if (MODE == 1) {
#pragma unroll
            for (int s = 0; s < 4; s++) {
                int idx = tid + (s << 8);
                int c = idx >> 5, n = (idx & 31) << 2;
                int cg = kt * 32 + c;
                float4 y = *(const float4*)&Bsrc[(size_t)cg * NNc + n0 + n];
                float sc = g_scale[cg], sh = g_shift[cg];
                uint4 u;
                u.x = to_tf32(fmaxf(fmaf(sc, y.x, sh), 0.f));
                u.y = to_tf32(fmaxf(fmaf(sc, y.y, sh), 0.f));
                u.z = to_tf32(fmaxf(fmaf(sc, y.z, sh), 0.f));
                u.w = to_tf32(fmaxf(fmaf(sc, y.w, sh), 0.f));
                *(uint4*)&sB[c * SBS + n] = u;
            }
        } else {
#pragma unroll
            for (int s = 0; s < 4; s++) {
                int idx = tid + (s << 8);
                int c4u = idx >> 7, j = idx & 127;
                int col = n0 + j;
                int idxv = g_idx[col];
                int b   = col >> 15;
                int cl0 = c4u << 2;
                int cg0 = kt * 32 + cl0;
                uint32_t v0, v1, v2, v3;
                if (cg0 + 3 < 128) {
                    float4 f = *(const float4*)&g_featT[((size_t)b * Np + idxv) * Cf + cg0];
                    v0 = to_tf32(f.x); v1 = to_tf32(f.y);
                    v2 = to_tf32(f.z); v3 = to_tf32(f.w);
                } else {
                    int q = col >> 5;
                    float f[4];
#pragma unroll
                    for (int i = 0; i < 4; i++) {
                        int cg = cg0 + i;
                        float x = 0.f;
                        if (cg < 128)
                            x = g_featT[((size_t)b * Np + idxv) * Cf + cg];
                        else if (cg < 131)
                            x = pxyz[((size_t)b * Np + idxv) * 3 + cg - 128]
                              - nxyz[q * 3 + cg - 128];
                        f[i] = x;
                    }
                    v0 = to_tf32(f[0]); v1 = to_tf32(f[1]);
                    v2 = to_tf32(f[2]); v3 = to_tf32(f[3]);
                }
                sB[(cl0 + 0) * SBS + j] = v0;
                sB[(cl0 + 1) * SBS + j] = v1;
                sB[(cl0 + 2) * SBS + j] = v2;
                sB[(cl0 + 3) * SBS + j] = v3;
            }
        }
        asm volatile("cp.async.wait_all;" ::: "memory");
        __syncthreads();

        // ---- compute: 4 k-steps of 8 ----
#pragma unroll
        for (int ks = 0; ks < 4; ks++) {
            uint32_t a[4][4], bf[4][2];
            const int arow = (ks * 8 + (lane & 3)) * SBS + wm * 64 + (lane >> 2);
#pragma unroll
            for (int mt = 0; mt < 4; mt++) {
                int p = arow + mt * 16;
                a[mt][0] = sA[p];
                a[mt][1] = sA[p + 8];
                a[mt][2] = sA[p + 4 * SBS];
                a[mt][3] = sA[p + 4 * SBS + 8];
            }
            const int brow = (ks * 8 + (lane & 3)) * SBS + wn * 32 + (lane >> 2);
#pragma unroll
            for (int nt = 0; nt < 4; nt++) {
                int p = brow + nt * 8;
                bf[nt][0] = sB[p];
                bf[nt][1] = sB[p + 4 * SBS];
            }
#pragma unroll
            for (int mt = 0; mt < 4; mt++)
#pragma unroll
                for (int nt = 0; nt < 4; nt++)
                    MMA1688(acc[mt][nt], a[mt], bf[nt]);
        }
    }

    // ---- epilogue: bias add, store Y, per-channel partial stats ----
    const int qid = lane >> 2;
    const int qt  = lane & 3;
#pragma unroll
    for (int mt = 0; mt < 4; mt++) {
        int m1 = wm * 64 + mt * 16 + qid;
        int m2 = m1 + 8;
        float bb1 = bias[o0 + m1], bb2 = bias[o0 + m2];
        float s1 = 0.f, q1 = 0.f, s2 = 0.f, q2 = 0.f;
#pragma unroll
        for (int nt = 0; nt < 4; nt++) {
            int n = n0 + wn * 32 + nt * 8 + qt * 2;
            float v0 = acc[mt][nt][0] + bb1, v1 = acc[mt][nt][1] + bb1;
            float v2 = acc[mt][nt][2] + bb2, v3 = acc[mt][nt][3] + bb2;
            *(float2*)&Y[(size_t)(o0 + m1) * NNc + n] = make_float2(v0, v1);
            *(float2*)&Y[(size_t)(o0 + m2) * NNc + n] = make_float2(v2, v3);
            s1 += v0 + v1; q1 += v0 * v0 + v1 * v1;
            s2 += v2 + v3; q2 += v2 * v2 + v3 * v3;
        }
        s1 += __shfl_xor_sync(0xffffffffu, s1, 1); s1 += __shfl_xor_sync(0xffffffffu, s1, 2);
        q1 += __shfl_xor_sync(0xffffffffu, q1, 1); q1 += __shfl_xor_sync(0xffffffffu, q1, 2);
        s2 += __shfl_xor_sync(0xffffffffu, s2, 1); s2 += __shfl_xor_sync(0xffffffffu, s2, 2);
        q2 += __shfl_xor_sync(0xffffffffu, q2, 1); q2 += __shfl_xor_sync(0xffffffffu, q2, 2);
        if (qt == 0) {
            atomicAdd(&s_sum[m1], s1); atomicAdd(&s_sq[m1], q1);
            atomicAdd(&s_sum[m2], s2); atomicAdd(&s_sq[m2], q2);
        }
    }
    __syncthreads();
    if (tid < 128) {
        g_ps[(size_t)(o0 + tid) * NCTA + blockIdx.x] = s_sum[tid];
        g_pq[(size_t)(o0 + tid) * NCTA + blockIdx.x] = s_sq[tid];
    }
}

// ---------------- kernel: reduce partials -> BN scale/shift ----------------
__global__ void k_reduce(const float* __restrict__ gam, const float* __restrict__ bet)
{
    __shared__ float ss[256], sq[256];
    int c = blockIdx.x, t = threadIdx.x;
    float s = g_ps[(size_t)c * NCTA + t]       + g_ps[(size_t)c * NCTA + 256 + t]
            + g_ps[(size_t)c * NCTA + 512 + t] + g_ps[(size_t)c * NCTA + 768 + t];
    float q = g_pq[(size_t)c * NCTA + t]       + g_pq[(size_t)c * NCTA + 256 + t]
            + g_pq[(size_t)c * NCTA + 512 + t] + g_pq[(size_t)c * NCTA + 768 + t];
    ss[t] = s; sq[t] = q;
    __syncthreads();
    for (int st = 128; st > 0; st >>= 1) {
        if (t < st) { ss[t] += ss[t + st]; sq[t] += sq[t + st]; }
        __syncthreads();
    }
    if (t == 0) {
        float mean = ss[0] * (1.f / NNc);
        float var  = sq[0] * (1.f / NNc) - mean * mean;
        float rs   = rsqrtf(var + EPSv);
        float sc   = gam[c] * rs;
        g_scale[c] = sc;
        g_shift[c] = fmaf(-mean, sc, bet[c]);
    }
}

// ---------------- kernel: BN3 + ReLU + max over K ----------------
__global__ void k_final(const float* __restrict__ Y3, float* __restrict__ outf)
{
    int i = blockIdx.x * blockDim.x + threadIdx.x;
    int m = i & (Mq - 1);
    int o = (i >> 10) & 255;
    int b = i >> 18;
    size_t base = (size_t)o * NNc + (((size_t)b << 10) + m) * Kq;
    const float4* p = (const float4*)(Y3 + base);
    float sc = g_scale[o], sh = g_shift[o];
    float mx = 0.f;
#pragma unroll
    for (int t = 0; t < 8; t++) {
        float4 v = p[t];
        mx = fmaxf(mx, fmaxf(fmaf(sc, v.x, sh), 0.f));
        mx = fmaxf(mx, fmaxf(fmaf(sc, v.y, sh), 0.f));
        mx = fmaxf(mx, fmaxf(fmaf(sc, v.z, sh), 0.f));
        mx = fmaxf(mx, fmaxf(fmaf(sc, v.w, sh), 0.f));
    }
    outf[((size_t)b * 256 + o) * Mq + m] = mx;
}

// ---------------- host launcher ----------------
extern "C" void kernel_launch(void* const* d_in, const int* in_sizes, int n_in,
                              void* d_out, int out_size)
{
    const float* pxyz = (const float*)d_in[0];
    const float* feat = (const float*)d_in[1];
    const int*   ind  = (const int*)d_in[2];
    const float* w1 = (const float*)d_in[3];  const float* b1 = (const float*)d_in[4];
    const float* g1 = (const float*)d_in[5];  const float* be1 = (const float*)d_in[6];
    const float* w2 = (const float*)d_in[7];  const float* b2 = (const float*)d_in[8];
    const float* g2 = (const float*)d_in[9];  const float* be2 = (const float*)d_in[10];
    const float* w3 = (const float*)d_in[11]; const float* b3 = (const float*)d_in[12];
    const float* g3 = (const float*)d_in[13]; const float* be3 = (const float*)d_in[14];

    float* out  = (float*)d_out;
    float* nxyz = out;
    float* fout = out + Bb * Mq * 3;

    float *pY1, *pY2, *pY3, *pFT, *pWt;
    cudaGetSymbolAddress((void**)&pY1, g_Y1);
    cudaGetSymbolAddress((void**)&pY2, g_Y2);
    cudaGetSymbolAddress((void**)&pY3, g_Y3);
    cudaGetSymbolAddress((void**)&pFT, g_featT);
    cudaGetSymbolAddress((void**)&pWt, g_Wt);

    const int W2_OFF = KCP1 * 128;
    const int W3_OFF = KCP1 * 128 + 128 * 128;

    k_newxyz<<<(Bb * Mq + 255) / 256, 256>>>(pxyz, ind, nxyz);
    k_ballquery<<<(Bb * Mq * 32) / 256, 256>>>(pxyz, nxyz);
    k_transpose<<<dim3(Np / 32, Cf / 32, Bb), dim3(32, 8)>>>(feat, pFT);

    k_packWt<<<KCP1, 128>>>(w1, pWt, 131, 128, 1);
    k_packWt<<<128, 128>>>(w2, pWt + W2_OFF, 128, 128, 0);
    k_packWt<<<128, 256>>>(w3, pWt + W3_OFF, 128, 256, 0);

    // layer 1: fused gather/concat, K = 160 -> 5 chunks
    k_gemm_tf32<0><<<dim3(NCTA, 1), 256>>>(pWt, b1, 5, 128,
                                           nullptr, pxyz, nxyz, pY1);
    k_reduce<<<128, 256>>>(g1, be1);

    // layer 2: fused BN1+ReLU, K = 128 -> 4 chunks
    k_gemm_tf32<1><<<dim3(NCTA, 1), 256>>>(pWt + W2_OFF, b2, 4, 128,
                                           pY1, nullptr, nullptr, pY2);
    k_reduce<<<128, 256>>>(g2, be2);

    // layer 3: fused BN2+ReLU, 256 out channels
    k_gemm_tf32<1><<<dim3(NCTA, 2), 256>>>(pWt + W3_OFF, b3, 4, 256,
                                           pY2, nullptr, nullptr, pY3);
    k_reduce<<<256, 256>>>(g3, be3);

    k_final<<<(Bb * 256 * Mq) / 256, 256>>>(pY3, fout);
}

// round 7
// speedup vs baseline: 2.2363x; 1.1081x over previous
#include <cuda_runtime.h>
#include <cuda_bf16.h>
#include <cstdint>
#include <cstddef>

// ---------------- problem constants ----------------
#define Bb   4
#define Np   16384
#define Cf   128
#define Mq   1024
#define Kq   32
#define NNc  131072            // Bb*Mq*Kq (GEMM column count)
#define R2c  0.16f
#define EPSv 1e-5f
#define KCP1 160               // layer1 K padded (131 -> 160 = 5 chunks of 32)
#define NCTA 1024
#define NQ   4096              // total queries (B*M)

// ---------------- scratch (device globals) ----------------
__device__ int   g_idx[NNc];
__device__ float g_Wt[KCP1*128 + 128*128 + 128*256];   // tf32-rounded, [c][o]
__device__ float g_featT[(size_t)Bb * Np * Cf];        // 32 MB
__device__ float g_Y1[(size_t)128 * NNc];              // 64 MB
__device__ float g_Y2[(size_t)128 * NNc];              // 64 MB
__device__ float g_mx[(size_t)256 * NQ];               // 4 MB  (layer3 raw max over K)
__device__ float g_ps[256 * NCTA];
__device__ float g_pq[256 * NCTA];
__device__ float g_scale[256];
__device__ float g_shift[256];

// ---------------- helpers ----------------
__device__ __forceinline__ uint32_t smem_u32(const void* p) {
    uint32_t a;
    asm("{ .reg .u64 t; cvta.to.shared.u64 t, %1; cvt.u32.u64 %0, t; }" : "=r"(a) : "l"(p));
    return a;
}
__device__ __forceinline__ uint32_t to_tf32(float x) {
    uint32_t u;
    asm("cvt.rna.tf32.f32 %0, %1;" : "=r"(u) : "f"(x));
    return u;
}
#define CPASYNC16(dst, src) \
    asm volatile("cp.async.ca.shared.global [%0],[%1],16;" :: "r"(dst), "l"(src))
#define MMA1688(c, a, b) \
    asm volatile("mma.sync.aligned.m16n8k8.row.col.f32.tf32.tf32.f32 " \
                 "{%0,%1,%2,%3},{%4,%5,%6,%7},{%8,%9},{%0,%1,%2,%3};" \
                 : "+f"((c)[0]),"+f"((c)[1]),"+f"((c)[2]),"+f"((c)[3]) \
                 : "r"((a)[0]),"r"((a)[1]),"r"((a)[2]),"r"((a)[3]), \
                   "r"((b)[0]),"r"((b)[1]))

// ---------------- kernel: gather new_xyz ----------------
__global__ void k_newxyz(const float* __restrict__ pxyz, const int* __restrict__ ind,
                         float* __restrict__ out)
{
    int i = blockIdx.x * blockDim.x + threadIdx.x;
    if (i >= Bb * Mq) return;
    int b = i >> 10;
    int n = ind[i];
    const float* p = pxyz + ((size_t)b * Np + n) * 3;
    out[i * 3 + 0] = p[0];
    out[i * 3 + 1] = p[1];
    out[i * 3 + 2] = p[2];
}

// ---------------- kernel: ball query (warp per query) ----------------
__global__ void k_ballquery(const float* __restrict__ pxyz, const float* __restrict__ nxyz)
{
    int gtid = blockIdx.x * blockDim.x + threadIdx.x;
    int q    = gtid >> 5;
    int lane = gtid & 31;
    int b    = q >> 10;

    float nx = nxyz[q * 3 + 0], ny = nxyz[q * 3 + 1], nz = nxyz[q * 3 + 2];
    const float* px = pxyz + (size_t)b * Np * 3;

    int cnt = 0, first = 0;
    for (int n0 = 0; n0 < Np; n0 += 32) {
        int n = n0 + lane;
        float dx = px[n * 3 + 0] - nx, dy = px[n * 3 + 1] - ny, dz = px[n * 3 + 2] - nz;
        float d2 = __fadd_rn(__fadd_rn(__fmul_rn(dx, dx), __fmul_rn(dy, dy)), __fmul_rn(dz, dz));
        bool within = d2 < R2c;
        unsigned bal = __ballot_sync(0xffffffffu, within);
        if (bal) {
            if (cnt == 0) first = n0 + __ffs(bal) - 1;
            int pre = __popc(bal & ((1u << lane) - 1u));
            if (within && (cnt + pre) < Kq) g_idx[q * Kq + cnt + pre] = n;
            cnt += __popc(bal);
            if (cnt >= Kq) break;
        }
    }
    cnt = min(cnt, Kq);
    if (lane >= cnt) g_idx[q * Kq + lane] = first;
}

// ---------------- kernel: transpose features -> featT[b][n][c] ----------------
__global__ void k_transpose(const float* __restrict__ f, float* __restrict__ ft)
{
    __shared__ float t[32][33];
    int b  = blockIdx.z;
    int n0 = blockIdx.x << 5, c0 = blockIdx.y << 5;
    int tx = threadIdx.x, ty = threadIdx.y;       // 32 x 8
#pragma unroll
    for (int i = 0; i < 32; i += 8)
        t[ty + i][tx] = f[((size_t)b * Cf + c0 + ty + i) * Np + n0 + tx];
    __syncthreads();
#pragma unroll
    for (int i = 0; i < 32; i += 8)
        ft[((size_t)b * Np + n0 + ty + i) * Cf + c0 + tx] = t[tx][ty + i];
}

// ---------------- kernel: pack weights -> tf32 transposed Wt[c][o] ----------------
__global__ void k_packWt(const float* __restrict__ W, float* __restrict__ Wt,
                         int KC, int Osz, int perm)
{
    int c = blockIdx.x, o = threadIdx.x;
    float v = 0.f;
    if (perm) {
        int oc = (c < 128) ? (c + 3) : ((c < 131) ? (c - 128) : -1);
        if (oc >= 0) v = W[o * 131 + oc];
    } else if (c < KC) {
        v = W[o * KC + c];
    }
    uint32_t u = to_tf32(v);
    Wt[c * Osz + o] = __uint_as_float(u);
}

// ---------------- fused tf32 GEMM (double-buffered) ----------------
// Y[o][n] = sum_c W[o][c] * X[n][c] + bias[o]; per-CTA channel partial stats.
// CTA tile 128(M) x 128(N), K-chunk 32; 8 warps 2(M)x4(N), warp tile 64x32.
// MODE 0: B generated by gather/concat on the fly (layer 1)
// MODE 1: B = relu(scale*Yprev + shift) (layers 2/3)
// DOMAX 1: don't write Y; write per-(row, query) max of accumulators to g_mx.
#define SBS   136                 // smem row stride in 4B elems
#define BUFW  (32 * SBS)          // one buffer in words
template <int MODE, int DOMAX>
__global__ void __launch_bounds__(256, 2) k_gemm_tf32(
    const float* __restrict__ Wt, const float* __restrict__ bias,
    int kchunks, int Osz,
    const float* __restrict__ Bsrc,
    const float* __restrict__ pxyz, const float* __restrict__ nxyz,
    float* __restrict__ Y)
{
    extern __shared__ uint32_t dsm[];     // [2*BUFW A][2*BUFW B]
    __shared__ float s_sum[128], s_sq[128];

    const int tid  = threadIdx.x;
    const int wid  = tid >> 5, lane = tid & 31;
    const int n0   = blockIdx.x << 7;
    const int o0   = blockIdx.y << 7;
    const int wm   = wid >> 2;
    const int wn   = wid & 3;

    if (tid < 128) { s_sum[tid] = 0.f; s_sq[tid] = 0.f; }

    float acc[4][4][4];
#pragma unroll
    for (int mt = 0; mt < 4; mt++)
#pragma unroll
        for (int nt = 0; nt < 4; nt++)
#pragma unroll
            for (int r = 0; r < 4; r++) acc[mt][nt][r] = 0.f;

    uint32_t pv[16];

    // ---------- helpers as macros over local state ----------
#define STAGE_A(KT, BUF) do {                                                  \
    uint32_t base = smem_u32(dsm) + (BUF) * (BUFW * 4);                        \
    _Pragma("unroll")                                                          \
    for (int s = 0; s < 4; s++) {                                              \
        int idx = tid + (s << 8);                                              \
        int c = idx >> 5, seg = idx & 31;                                      \
        const float* src = Wt + (size_t)((KT) * 32 + c) * Osz + o0 + seg * 4;  \
        CPASYNC16(base + (c * SBS + seg * 4) * 4, src);                        \
    } } while (0)

#define PREFETCH_B(KT) do {                                                    \
    if (MODE == 1) {                                                           \
        _Pragma("unroll")                                                      \
        for (int s = 0; s < 4; s++) {                                          \
            int idx = tid + (s << 8);                                          \
            int c = idx >> 5, n = (idx & 31) << 2;                             \
            int cg = (KT) * 32 + c;                                            \
            float4 y = *(const float4*)&Bsrc[(size_t)cg * NNc + n0 + n];       \
            float sc = g_scale[cg], sh = g_shift[cg];                          \
            pv[s*4+0] = to_tf32(fmaxf(fmaf(sc, y.x, sh), 0.f));                \
            pv[s*4+1] = to_tf32(fmaxf(fmaf(sc, y.y, sh), 0.f));                \
            pv[s*4+2] = to_tf32(fmaxf(fmaf(sc, y.z, sh), 0.f));                \
            pv[s*4+3] = to_tf32(fmaxf(fmaf(sc, y.w, sh), 0.f));                \
        }                                                                      \
    } else {                                                                   \
        _Pragma("unroll")                                                      \
        for (int s = 0; s < 4; s++) {                                          \
            int idx = tid + (s << 8);                                          \
            int c4u = idx >> 7, j = idx & 127;                                 \
            int col = n0 + j;                                                  \
            int idxv = g_idx[col];                                             \
            int b = col >> 15;                                                 \
            int cl0 = c4u << 2;                                                \
            int cg0 = (KT) * 32 + cl0;                                         \
            if (cg0 + 3 < 128) {                                               \
                float4 f = *(const float4*)&g_featT[((size_t)b*Np+idxv)*Cf+cg0]; \
                pv[s*4+0] = to_tf32(f.x); pv[s*4+1] = to_tf32(f.y);            \
                pv[s*4+2] = to_tf32(f.z); pv[s*4+3] = to_tf32(f.w);            \
            } else {                                                           \
                int q = col >> 5;                                              \
                _Pragma("unroll")                                              \
                for (int i2 = 0; i2 < 4; i2++) {                               \
                    int cg = cg0 + i2;                                         \
                    float x = 0.f;                                             \
                    if (cg < 128)                                              \
                        x = g_featT[((size_t)b * Np + idxv) * Cf + cg];        \
                    else if (cg < 131)                                         \
                        x = pxyz[((size_t)b * Np + idxv) * 3 + cg - 128]       \
                          - nxyz[q * 3 + cg - 128];                            \
                    pv[s*4+i2] = to_tf32(x);                                   \
                }                                                              \
            }                                                                  \
        }                                                                      \
    } } while (0)

#define STAGE_B(BUF) do {                                                      \
    uint32_t* sBc = dsm + 2 * BUFW + (BUF) * BUFW;                             \
    if (MODE == 1) {                                                           \
        _Pragma("unroll")                                                      \
        for (int s = 0; s < 4; s++) {                                          \
            int idx = tid + (s << 8);                                          \
            int c = idx >> 5, n = (idx & 31) << 2;                             \
            uint4 u; u.x = pv[s*4+0]; u.y = pv[s*4+1];                         \
            u.z = pv[s*4+2]; u.w = pv[s*4+3];                                  \
            *(uint4*)&sBc[c * SBS + n] = u;                                    \
        }                                                                      \
    } else {                                                                   \
        _Pragma("unroll")                                                      \
        for (int s = 0; s < 4; s++) {                                          \
            int idx = tid + (s << 8);                                          \
            int c4u = idx >> 7, j = idx & 127;                                 \
            int cl0 = c4u << 2;                                                \
            sBc[(cl0 + 0) * SBS + j] = pv[s*4+0];                              \
            sBc[(cl0 + 1) * SBS + j] = pv[s*4+1];                              \
            sBc[(cl0 + 2) * SBS + j] = pv[s*4+2];                              \
            sBc[(cl0 + 3) * SBS + j] = pv[s*4+3];                              \
        }                                                                      \
    } } while (0)

    // ---------- prologue: chunk 0 into buffer 0 ----------
    PREFETCH_B(0);
    STAGE_A(0, 0);
    STAGE_B(0);
    asm volatile("cp.async.wait_all;" ::: "memory");
    __syncthreads();

    // ---------- pipelined mainloop ----------
    for (int kt = 0; kt < kchunks; kt++) {
        const int cur = kt & 1, nxt = cur ^ 1;
        const bool more = (kt + 1 < kchunks);
        if (more) {
            STAGE_A(kt + 1, nxt);     // cp.async (async, lands in nxt)
            PREFETCH_B(kt + 1);       // LDG into regs, overlaps compute below
        }

        const uint32_t* sA = dsm + cur * BUFW;
        const uint32_t* sB = dsm + 2 * BUFW + cur * BUFW;
#pragma unroll
        for (int ks = 0; ks < 4; ks++) {
            uint32_t a[4][4], bf[4][2];
            const int arow = (ks * 8 + (lane & 3)) * SBS + wm * 64 + (lane >> 2);
#pragma unroll
            for (int mt = 0; mt < 4; mt++) {
                int p = arow + mt * 16;
                a[mt][0] = sA[p];
                a[mt][1] = sA[p + 8];
                a[mt][2] = sA[p + 4 * SBS];
                a[mt][3] = sA[p + 4 * SBS + 8];
            }
            const int brow = (ks * 8 + (lane & 3)) * SBS + wn * 32 + (lane >> 2);
#pragma unroll
            for (int nt = 0; nt < 4; nt++) {
                int p = brow + nt * 8;
                bf[nt][0] = sB[p];
                bf[nt][1] = sB[p + 4 * SBS];
            }
#pragma unroll
            for (int mt = 0; mt < 4; mt++)
#pragma unroll
                for (int nt = 0; nt < 4; nt++)
                    MMA1688(acc[mt][nt], a[mt], bf[nt]);
        }

        if (more) STAGE_B(nxt);       // regs -> alternate buffer (no race with cur)
        asm volatile("cp.async.wait_all;" ::: "memory");
        __syncthreads();
    }

    // ---------- epilogue ----------
    const int qid = lane >> 2;
    const int qt  = lane & 3;
#pragma unroll
    for (int mt = 0; mt < 4; mt++) {
        int m1 = wm * 64 + mt * 16 + qid;
        int m2 = m1 + 8;
        float bb1 = bias[o0 + m1], bb2 = bias[o0 + m2];
        float s1 = 0.f, q1 = 0.f, s2 = 0.f, q2 = 0.f;
        float mx1 = -3.4e38f, mx2 = -3.4e38f;
#pragma unroll
        for (int nt = 0; nt < 4; nt++) {
            float v0 = acc[mt][nt][0] + bb1, v1 = acc[mt][nt][1] + bb1;
            float v2 = acc[mt][nt][2] + bb2, v3 = acc[mt][nt][3] + bb2;
            if (!DOMAX) {
                int n = n0 + wn * 32 + nt * 8 + qt * 2;
                *(float2*)&Y[(size_t)(o0 + m1) * NNc + n] = make_float2(v0, v1);
                *(float2*)&Y[(size_t)(o0 + m2) * NNc + n] = make_float2(v2, v3);
            } else {
                mx1 = fmaxf(mx1, fmaxf(v0, v1));
                mx2 = fmaxf(mx2, fmaxf(v2, v3));
            }
            s1 += v0 + v1; q1 += v0 * v0 + v1 * v1;
            s2 += v2 + v3; q2 += v2 * v2 + v3 * v3;
        }
        s1 += __shfl_xor_sync(0xffffffffu, s1, 1); s1 += __shfl_xor_sync(0xffffffffu, s1, 2);
        q1 += __shfl_xor_sync(0xffffffffu, q1, 1); q1 += __shfl_xor_sync(0xffffffffu, q1, 2);
        s2 += __shfl_xor_sync(0xffffffffu, s2, 1); s2 += __shfl_xor_sync(0xffffffffu, s2, 2);
        q2 += __shfl_xor_sync(0xffffffffu, q2, 1); q2 += __shfl_xor_sync(0xffffffffu, q2, 2);
        if (DOMAX) {
            mx1 = fmaxf(mx1, __shfl_xor_sync(0xffffffffu, mx1, 1));
            mx1 = fmaxf(mx1, __shfl_xor_sync(0xffffffffu, mx1, 2));
            mx2 = fmaxf(mx2, __shfl_xor_sync(0xffffffffu, mx2, 1));
            mx2 = fmaxf(mx2, __shfl_xor_sync(0xffffffffu, mx2, 2));
            if (qt == 0) {
                int qidx = blockIdx.x * 4 + wn;    // warp tile N=32 == one query
                g_mx[(size_t)(o0 + m1) * NQ + qidx] = mx1;
                g_mx[(size_t)(o0 + m2) * NQ + qidx] = mx2;
            }
        }
        if (qt == 0) {
            atomicAdd(&s_sum[m1], s1); atomicAdd(&s_sq[m1], q1);
            atomicAdd(&s_sum[m2], s2); atomicAdd(&s_sq[m2], q2);
        }
    }
    __syncthreads();
    if (tid < 128) {
        g_ps[(size_t)(o0 + tid) * NCTA + blockIdx.x] = s_sum[tid];
        g_pq[(size_t)(o0 + tid) * NCTA + blockIdx.x] = s_sq[tid];
    }
#undef STAGE_A
#undef PREFETCH_B
#undef STAGE_B
}

// ---------------- kernel: reduce partials -> BN scale/shift ----------------
__global__ void k_reduce(const float* __restrict__ gam, const float* __restrict__ bet)
{
    __shared__ float ss[256], sq[256];
    int c = blockIdx.x, t = threadIdx.x;
    float s = g_ps[(size_t)c * NCTA + t]       + g_ps[(size_t)c * NCTA + 256 + t]
            + g_ps[(size_t)c * NCTA + 512 + t] + g_ps[(size_t)c * NCTA + 768 + t];
    float q = g_pq[(size_t)c * NCTA + t]       + g_pq[(size_t)c * NCTA + 256 + t]
            + g_pq[(size_t)c * NCTA + 512 + t] + g_pq[(size_t)c * NCTA + 768 + t];
    ss[t] = s; sq[t] = q;
    __syncthreads();
    for (int st = 128; st > 0; st >>= 1) {
        if (t < st) { ss[t] += ss[t + st]; sq[t] += sq[t + st]; }
        __syncthreads();
    }
    if (t == 0) {
        float mean = ss[0] * (1.f / NNc);
        float var  = sq[0] * (1.f / NNc) - mean * mean;
        float rs   = rsqrtf(var + EPSv);
        float sc   = gam[c] * rs;
        g_scale[c] = sc;
        g_shift[c] = fmaf(-mean, sc, bet[c]);
    }
}

// ---------------- kernel: BN3+ReLU applied to per-query max ----------------
__global__ void k_final(float* __restrict__ outf)
{
    int i = blockIdx.x * blockDim.x + threadIdx.x;   // 1048576
    int m = i & (Mq - 1);
    int o = (i >> 10) & 255;
    int b = i >> 18;
    float v = g_mx[(size_t)o * NQ + b * Mq + m];
    outf[((size_t)b * 256 + o) * Mq + m] = fmaxf(fmaf(g_scale[o], v, g_shift[o]), 0.f);
}

// ---------------- host launcher ----------------
extern "C" void kernel_launch(void* const* d_in, const int* in_sizes, int n_in,
                              void* d_out, int out_size)
{
    const float* pxyz = (const float*)d_in[0];
    const float* feat = (const float*)d_in[1];
    const int*   ind  = (const int*)d_in[2];
    const float* w1 = (const float*)d_in[3];  const float* b1 = (const float*)d_in[4];
    const float* g1 = (const float*)d_in[5];  const float* be1 = (const float*)d_in[6];
    const float* w2 = (const float*)d_in[7];  const float* b2 = (const float*)d_in[8];
    const float* g2 = (const float*)d_in[9];  const float* be2 = (const float*)d_in[10];
    const float* w3 = (const float*)d_in[11]; const float* b3 = (const float*)d_in[12];
    const float* g3 = (const float*)d_in[13]; const float* be3 = (const float*)d_in[14];

    float* out  = (float*)d_out;
    float* nxyz = out;
    float* fout = out + Bb * Mq * 3;

    float *pY1, *pY2, *pFT, *pWt;
    cudaGetSymbolAddress((void**)&pY1, g_Y1);
    cudaGetSymbolAddress((void**)&pY2, g_Y2);
    cudaGetSymbolAddress((void**)&pFT, g_featT);
    cudaGetSymbolAddress((void**)&pWt, g_Wt);

    const int DSM = 4 * BUFW * 4;   // 69632 bytes (A x2 + B x2)
    cudaFuncSetAttribute(k_gemm_tf32<0,0>, cudaFuncAttributeMaxDynamicSharedMemorySize, DSM);
    cudaFuncSetAttribute(k_gemm_tf32<1,0>, cudaFuncAttributeMaxDynamicSharedMemorySize, DSM);
    cudaFuncSetAttribute(k_gemm_tf32<1,1>, cudaFuncAttributeMaxDynamicSharedMemorySize, DSM);

    const int W2_OFF = KCP1 * 128;
    const int W3_OFF = KCP1 * 128 + 128 * 128;

    k_newxyz<<<(Bb * Mq + 255) / 256, 256>>>(pxyz, ind, nxyz);
    k_ballquery<<<(Bb * Mq * 32) / 256, 256>>>(pxyz, nxyz);
    k_transpose<<<dim3(Np / 32, Cf / 32, Bb), dim3(32, 8)>>>(feat, pFT);

    k_packWt<<<KCP1, 128>>>(w1, pWt, 131, 128, 1);
    k_packWt<<<128, 128>>>(w2, pWt + W2_OFF, 128, 128, 0);
    k_packWt<<<128, 256>>>(w3, pWt + W3_OFF, 128, 256, 0);

    // layer 1: fused gather/concat, K = 160 -> 5 chunks
    k_gemm_tf32<0,0><<<dim3(NCTA, 1), 256, DSM>>>(pWt, b1, 5, 128,
                                                  nullptr, pxyz, nxyz, pY1);
    k_reduce<<<128, 256>>>(g1, be1);

    // layer 2: fused BN1+ReLU, K = 128 -> 4 chunks
    k_gemm_tf32<1,0><<<dim3(NCTA, 1), 256, DSM>>>(pWt + W2_OFF, b2, 4, 128,
                                                  pY1, nullptr, nullptr, pY2);
    k_reduce<<<128, 256>>>(g2, be2);

    // layer 3: fused BN2+ReLU, 256 out channels, max fused into epilogue (no Y3)
    k_gemm_tf32<1,1><<<dim3(NCTA, 2), 256, DSM>>>(pWt + W3_OFF, b3, 4, 256,
                                                  pY2, nullptr, nullptr, nullptr);
    k_reduce<<<256, 256>>>(g3, be3);

    // BN3+ReLU on per-query maxima (4MB read, 4MB write)
    k_final<<<(Bb * 256 * Mq) / 256, 256>>>(fout);
}

// round 8
// speedup vs baseline: 2.3515x; 1.0515x over previous
#include <cuda_runtime.h>
#include <cuda_fp16.h>
#include <cstdint>
#include <cstddef>

// ---------------- problem constants ----------------
#define Bb   4
#define Np   16384
#define Cf   128
#define Mq   1024
#define Kq   32
#define NNc  131072            // Bb*Mq*Kq (GEMM column count)
#define R2c  0.16f
#define EPSv 1e-5f
#define KCP1 160               // layer1 K padded (131 -> 160 = 5 chunks of 32)
#define NCTA 1024
#define NQ   4096              // total queries (B*M)

// ---------------- scratch (device globals) ----------------
__device__ int   g_idx[NNc];
__device__ __align__(16) __half g_Whf[KCP1*128 + 128*128 + 128*256];  // fp16 W, [o][cpad]
__device__ float g_featT[(size_t)Bb * Np * Cf];        // 32 MB
__device__ float g_Y1[(size_t)128 * NNc];              // 64 MB
__device__ float g_Y2[(size_t)128 * NNc];              // 64 MB
__device__ float g_mx[(size_t)256 * NQ];               // 4 MB  (layer3 raw max over K)
__device__ float g_ps[256 * NCTA];
__device__ float g_pq[256 * NCTA];
__device__ float g_scale[256];
__device__ float g_shift[256];

// ---------------- helpers ----------------
__device__ __forceinline__ uint32_t smem_u32(const void* p) {
    uint32_t a;
    asm("{ .reg .u64 t; cvta.to.shared.u64 t, %1; cvt.u32.u64 %0, t; }" : "=r"(a) : "l"(p));
    return a;
}
// pack two floats into f16x2 (lo, hi)
__device__ __forceinline__ uint32_t f22h(float lo, float hi) {
    uint32_t r;
    asm("cvt.rn.f16x2.f32 %0, %1, %2;" : "=r"(r) : "f"(hi), "f"(lo));
    return r;
}
#define CPASYNC16(dst, src) \
    asm volatile("cp.async.ca.shared.global [%0],[%1],16;" :: "r"(dst), "l"(src))
#define LDSM_X4(d0,d1,d2,d3,a) \
    asm volatile("ldmatrix.sync.aligned.m8n8.x4.shared.b16 {%0,%1,%2,%3},[%4];" \
                 : "=r"(d0),"=r"(d1),"=r"(d2),"=r"(d3) : "r"(a))
#define LDSM_X2(d0,d1,a) \
    asm volatile("ldmatrix.sync.aligned.m8n8.x2.shared.b16 {%0,%1},[%2];" \
                 : "=r"(d0),"=r"(d1) : "r"(a))
#define MMA16816(c, a, b) \
    asm volatile("mma.sync.aligned.m16n8k16.row.col.f32.f16.f16.f32 " \
                 "{%0,%1,%2,%3},{%4,%5,%6,%7},{%8,%9},{%0,%1,%2,%3};" \
                 : "+f"((c)[0]),"+f"((c)[1]),"+f"((c)[2]),"+f"((c)[3]) \
                 : "r"((a)[0]),"r"((a)[1]),"r"((a)[2]),"r"((a)[3]), \
                   "r"((b)[0]),"r"((b)[1]))

// ---------------- kernel: gather new_xyz ----------------
__global__ void k_newxyz(const float* __restrict__ pxyz, const int* __restrict__ ind,
                         float* __restrict__ out)
{
    int i = blockIdx.x * blockDim.x + threadIdx.x;
    if (i >= Bb * Mq) return;
    int b = i >> 10;
    int n = ind[i];
    const float* p = pxyz + ((size_t)b * Np + n) * 3;
    out[i * 3 + 0] = p[0];
    out[i * 3 + 1] = p[1];
    out[i * 3 + 2] = p[2];
}

// ---------------- kernel: ball query (warp per query) ----------------
__global__ void k_ballquery(const float* __restrict__ pxyz, const float* __restrict__ nxyz)
{
    int gtid = blockIdx.x * blockDim.x + threadIdx.x;
    int q    = gtid >> 5;
    int lane = gtid & 31;
    int b    = q >> 10;

    float nx = nxyz[q * 3 + 0], ny = nxyz[q * 3 + 1], nz = nxyz[q * 3 + 2];
    const float* px = pxyz + (size_t)b * Np * 3;

    int cnt = 0, first = 0;
    for (int n0 = 0; n0 < Np; n0 += 32) {
        int n = n0 + lane;
        float dx = px[n * 3 + 0] - nx, dy = px[n * 3 + 1] - ny, dz = px[n * 3 + 2] - nz;
        float d2 = __fadd_rn(__fadd_rn(__fmul_rn(dx, dx), __fmul_rn(dy, dy)), __fmul_rn(dz, dz));
        bool within = d2 < R2c;
        unsigned bal = __ballot_sync(0xffffffffu, within);
        if (bal) {
            if (cnt == 0) first = n0 + __ffs(bal) - 1;
            int pre = __popc(bal & ((1u << lane) - 1u));
            if (within && (cnt + pre) < Kq) g_idx[q * Kq + cnt + pre] = n;
            cnt += __popc(bal);
            if (cnt >= Kq) break;
        }
    }
    cnt = min(cnt, Kq);
    if (lane >= cnt) g_idx[q * Kq + lane] = first;
}

// ---------------- kernel: transpose features -> featT[b][n][c] ----------------
__global__ void k_transpose(const float* __restrict__ f, float* __restrict__ ft)
{
    __shared__ float t[32][33];
    int b  = blockIdx.z;
    int n0 = blockIdx.x << 5, c0 = blockIdx.y << 5;
    int tx = threadIdx.x, ty = threadIdx.y;       // 32 x 8
#pragma unroll
    for (int i = 0; i < 32; i += 8)
        t[ty + i][tx] = f[((size_t)b * Cf + c0 + ty + i) * Np + n0 + tx];
    __syncthreads();
#pragma unroll
    for (int i = 0; i < 32; i += 8)
        ft[((size_t)b * Np + n0 + ty + i) * Cf + c0 + tx] = t[tx][ty + i];
}

// ---------------- kernel: pack weights -> fp16 [o][cpad] ----------------
__global__ void k_packW(const float* __restrict__ W, __half* __restrict__ Wh,
                        int KC, int KCpad, int perm)
{
    int o = blockIdx.x, c = threadIdx.x;
    if (c >= KCpad) return;
    float v = 0.f;
    if (perm) {
        // packed channel order: 0..127 = feat (orig 3..130), 128..130 = xyz (orig 0..2)
        int oc = (c < 128) ? (c + 3) : ((c < 131) ? (c - 128) : -1);
        if (oc >= 0) v = W[o * 131 + oc];
    } else if (c < KC) {
        v = W[o * KC + c];
    }
    Wh[o * KCpad + c] = __float2half_rn(v);
}

// ---------------- fused fp16 GEMM (double-buffered, ldmatrix + m16n8k16) ----------------
// Y[o][n] = sum_c W[o][c] * X[n][c] + bias[o]; per-CTA channel partial stats.
// CTA tile 128(M) x 128(N), K-chunk 32; 8 warps 2(M)x4(N), warp tile 64x32.
// MODE 0: B generated by gather/concat on the fly (layer 1)
// MODE 1: B = relu(scale*Yprev + shift) (layers 2/3)
// DOMAX 1: no Y write; per-(row, query) max of accumulators -> g_mx.
#define SSTR 40                   // smem row stride in halves (80B, ldmatrix conflict-free)
#define ABUF (128 * SSTR)         // one A buffer in halves (5120)
template <int MODE, int DOMAX>
__global__ void __launch_bounds__(256, 2) k_gemm_h(
    const __half* __restrict__ Wh, const float* __restrict__ bias,
    int kchunks, int KCpad,
    const float* __restrict__ Bsrc,
    const float* __restrict__ pxyz, const float* __restrict__ nxyz,
    float* __restrict__ Y)
{
    extern __shared__ __half dsm[];   // [A buf0][A buf1][B buf0][B buf1], each ABUF halves
    __shared__ float s_sum[128], s_sq[128];

    const int tid  = threadIdx.x;
    const int wid  = tid >> 5, lane = tid & 31;
    const int n0   = blockIdx.x << 7;
    const int o0   = blockIdx.y << 7;
    const int wm   = wid >> 2;
    const int wn   = wid & 3;

    if (tid < 128) { s_sum[tid] = 0.f; s_sq[tid] = 0.f; }

    float acc[4][4][4];
#pragma unroll
    for (int mt = 0; mt < 4; mt++)
#pragma unroll
        for (int nt = 0; nt < 4; nt++)
#pragma unroll
            for (int r = 0; r < 4; r++) acc[mt][nt][r] = 0.f;

    uint32_t pv[8];   // staged B halves (4 iters x 2 f16x2)

#define STAGE_A(KT, BUF) do {                                                  \
    uint32_t base = smem_u32(dsm) + (BUF) * (ABUF * 2);                        \
    _Pragma("unroll")                                                          \
    for (int s = 0; s < 2; s++) {                                              \
        int idx = tid + (s << 8);            /* 0..511 */                      \
        int row = idx >> 2, seg = idx & 3;                                     \
        const __half* src = Wh + (size_t)(o0 + row) * KCpad + (KT) * 32 + seg * 8; \
        CPASYNC16(base + row * (SSTR * 2) + seg * 16, src);                    \
    } } while (0)

#define PREFETCH_B(KT) do {                                                    \
    _Pragma("unroll")                                                          \
    for (int s = 0; s < 4; s++) {                                              \
        int idx = tid + (s << 8);                                              \
        int c4 = idx >> 7, j = idx & 127;    /* c4: 0..7, j: col in tile */    \
        int cg0 = (KT) * 32 + c4 * 4;                                          \
        float f0, f1, f2, f3;                                                  \
        if (MODE == 1) {                                                       \
            int n = n0 + j;                                                    \
            float y0 = Bsrc[(size_t)(cg0 + 0) * NNc + n];                      \
            float y1 = Bsrc[(size_t)(cg0 + 1) * NNc + n];                      \
            float y2 = Bsrc[(size_t)(cg0 + 2) * NNc + n];                      \
            float y3 = Bsrc[(size_t)(cg0 + 3) * NNc + n];                      \
            f0 = fmaxf(fmaf(g_scale[cg0 + 0], y0, g_shift[cg0 + 0]), 0.f);     \
            f1 = fmaxf(fmaf(g_scale[cg0 + 1], y1, g_shift[cg0 + 1]), 0.f);     \
            f2 = fmaxf(fmaf(g_scale[cg0 + 2], y2, g_shift[cg0 + 2]), 0.f);     \
            f3 = fmaxf(fmaf(g_scale[cg0 + 3], y3, g_shift[cg0 + 3]), 0.f);     \
        } else {                                                               \
            int col = n0 + j;                                                  \
            int idxv = g_idx[col];                                             \
            int b = col >> 15;                                                 \
            if (cg0 + 3 < 128) {                                               \
                float4 f = *(const float4*)&g_featT[((size_t)b*Np+idxv)*Cf+cg0]; \
                f0 = f.x; f1 = f.y; f2 = f.z; f3 = f.w;                        \
            } else {                                                           \
                int q = col >> 5;                                              \
                float fv[4];                                                   \
                _Pragma("unroll")                                              \
                for (int i2 = 0; i2 < 4; i2++) {                               \
                    int cg = cg0 + i2;                                         \
                    float x = 0.f;                                             \
                    if (cg < 128)                                              \
                        x = g_featT[((size_t)b * Np + idxv) * Cf + cg];        \
                    else if (cg < 131)                                         \
                        x = pxyz[((size_t)b * Np + idxv) * 3 + cg - 128]       \
                          - nxyz[q * 3 + cg - 128];                            \
                    fv[i2] = x;                                                \
                }                                                              \
                f0 = fv[0]; f1 = fv[1]; f2 = fv[2]; f3 = fv[3];                \
            }                                                                  \
        }                                                                      \
        pv[s * 2 + 0] = f22h(f0, f1);                                          \
        pv[s * 2 + 1] = f22h(f2, f3);                                          \
    } } while (0)

#define STAGE_B(BUF) do {                                                      \
    __half* sBc = dsm + 2 * ABUF + (BUF) * ABUF;                               \
    _Pragma("unroll")                                                          \
    for (int s = 0; s < 4; s++) {                                              \
        int idx = tid + (s << 8);                                              \
        int c4 = idx >> 7, j = idx & 127;                                      \
        *(uint2*)&sBc[j * SSTR + c4 * 4] = make_uint2(pv[s*2+0], pv[s*2+1]);   \
    } } while (0)

    // ---------- prologue ----------
    PREFETCH_B(0);
    STAGE_A(0, 0);
    STAGE_B(0);
    asm volatile("cp.async.wait_all;" ::: "memory");
    __syncthreads();

    // ldmatrix lane addressing (byte offsets into a buffer)
    const uint32_t rowA = ((wm * 64 + (lane & 15)) * SSTR + (lane >> 4) * 8) * 2;
    const uint32_t rowB = ((wn * 32 + (lane & 7)) * SSTR + ((lane >> 3) & 1) * 8) * 2;

    // ---------- pipelined mainloop ----------
    for (int kt = 0; kt < kchunks; kt++) {
        const int cur = kt & 1, nxt = cur ^ 1;
        const bool more = (kt + 1 < kchunks);
        if (more) {
            STAGE_A(kt + 1, nxt);      // async into alternate buffer
            PREFETCH_B(kt + 1);        // LDG into regs, overlaps MMA below
        }

        const uint32_t bA = smem_u32(dsm) + cur * (ABUF * 2);
        const uint32_t bB = smem_u32(dsm) + (2 + cur) * (ABUF * 2);
#pragma unroll
        for (int ks = 0; ks < 2; ks++) {
            uint32_t ah[4][4], bh[4][2];
#pragma unroll
            for (int mt = 0; mt < 4; mt++) {
                uint32_t off = rowA + mt * (16 * SSTR * 2) + ks * 32;
                LDSM_X4(ah[mt][0], ah[mt][1], ah[mt][2], ah[mt][3], bA + off);
            }
#pragma unroll
            for (int nt = 0; nt < 4; nt++) {
                uint32_t off = rowB + nt * (8 * SSTR * 2) + ks * 32;
                LDSM_X2(bh[nt][0], bh[nt][1], bB + off);
            }
#pragma unroll
            for (int mt = 0; mt < 4; mt++)
#pragma unroll
                for (int nt = 0; nt < 4; nt++)
                    MMA16816(acc[mt][nt], ah[mt], bh[nt]);
        }

        if (more) STAGE_B(nxt);
        asm volatile("cp.async.wait_all;" ::: "memory");
        __syncthreads();
    }

    // ---------- epilogue ----------
    const int qid = lane >> 2;
    const int qt  = lane & 3;
#pragma unroll
    for (int mt = 0; mt < 4; mt++) {
        int m1 = wm * 64 + mt * 16 + qid;
        int m2 = m1 + 8;
        float bb1 = bias[o0 + m1], bb2 = bias[o0 + m2];
        float s1 = 0.f, q1 = 0.f, s2 = 0.f, q2 = 0.f;
        float mx1 = -3.4e38f, mx2 = -3.4e38f;
#pragma unroll
        for (int nt = 0; nt < 4; nt++) {
            float v0 = acc[mt][nt][0] + bb1, v1 = acc[mt][nt][1] + bb1;
            float v2 = acc[mt][nt][2] + bb2, v3 = acc[mt][nt][3] + bb2;
            if (!DOMAX) {
                int n = n0 + wn * 32 + nt * 8 + qt * 2;
                *(float2*)&Y[(size_t)(o0 + m1) * NNc + n] = make_float2(v0, v1);
                *(float2*)&Y[(size_t)(o0 + m2) * NNc + n] = make_float2(v2, v3);
            } else {
                mx1 = fmaxf(mx1, fmaxf(v0, v1));
                mx2 = fmaxf(mx2, fmaxf(v2, v3));
            }
            s1 += v0 + v1; q1 += v0 * v0 + v1 * v1;
            s2 += v2 + v3; q2 += v2 * v2 + v3 * v3;
        }
        s1 += __shfl_xor_sync(0xffffffffu, s1, 1); s1 += __shfl_xor_sync(0xffffffffu, s1, 2);
        q1 += __shfl_xor_sync(0xffffffffu, q1, 1); q1 += __shfl_xor_sync(0xffffffffu, q1, 2);
        s2 += __shfl_xor_sync(0xffffffffu, s2, 1); s2 += __shfl_xor_sync(0xffffffffu, s2, 2);
        q2 += __shfl_xor_sync(0xffffffffu, q2, 1); q2 += __shfl_xor_sync(0xffffffffu, q2, 2);
        if (DOMAX) {
            mx1 = fmaxf(mx1, __shfl_xor_sync(0xffffffffu, mx1, 1));
            mx1 = fmaxf(mx1, __shfl_xor_sync(0xffffffffu, mx1, 2));
            mx2 = fmaxf(mx2, __shfl_xor_sync(0xffffffffu, mx2, 1));
            mx2 = fmaxf(mx2, __shfl_xor_sync(0xffffffffu, mx2, 2));
            if (qt == 0) {
                int qidx = blockIdx.x * 4 + wn;     // warp tile N=32 == one query
                g_mx[(size_t)(o0 + m1) * NQ + qidx] = mx1;
                g_mx[(size_t)(o0 + m2) * NQ + qidx] = mx2;
            }
        }
        if (qt == 0) {
            atomicAdd(&s_sum[m1], s1); atomicAdd(&s_sq[m1], q1);
            atomicAdd(&s_sum[m2], s2); atomicAdd(&s_sq[m2], q2);
        }
    }
    __syncthreads();
    if (tid < 128) {
        g_ps[(size_t)(o0 + tid) * NCTA + blockIdx.x] = s_sum[tid];
        g_pq[(size_t)(o0 + tid) * NCTA + blockIdx.x] = s_sq[tid];
    }
#undef STAGE_A
#undef PREFETCH_B
#undef STAGE_B
}

// ---------------- kernel: reduce partials -> BN scale/shift ----------------
__global__ void k_reduce(const float* __restrict__ gam, const float* __restrict__ bet)
{
    __shared__ float ss[256], sq[256];
    int c = blockIdx.x, t = threadIdx.x;
    float s = g_ps[(size_t)c * NCTA + t]       + g_ps[(size_t)c * NCTA + 256 + t]
            + g_ps[(size_t)c * NCTA + 512 + t] + g_ps[(size_t)c * NCTA + 768 + t];
    float q = g_pq[(size_t)c * NCTA + t]       + g_pq[(size_t)c * NCTA + 256 + t]
            + g_pq[(size_t)c * NCTA + 512 + t] + g_pq[(size_t)c * NCTA + 768 + t];
    ss[t] = s; sq[t] = q;
    __syncthreads();
    for (int st = 128; st > 0; st >>= 1) {
        if (t < st) { ss[t] += ss[t + st]; sq[t] += sq[t + st]; }
        __syncthreads();
    }
    if (t == 0) {
        float mean = ss[0] * (1.f / NNc);
        float var  = sq[0] * (1.f / NNc) - mean * mean;
        float rs   = rsqrtf(var + EPSv);
        float sc   = gam[c] * rs;
        g_scale[c] = sc;
        g_shift[c] = fmaf(-mean, sc, bet[c]);
    }
}

// ---------------- kernel: BN3+ReLU applied to per-query max ----------------
__global__ void k_final(float* __restrict__ outf)
{
    int i = blockIdx.x * blockDim.x + threadIdx.x;   // 1048576
    int m = i & (Mq - 1);
    int o = (i >> 10) & 255;
    int b = i >> 18;
    float v = g_mx[(size_t)o * NQ + b * Mq + m];
    outf[((size_t)b * 256 + o) * Mq + m] = fmaxf(fmaf(g_scale[o], v, g_shift[o]), 0.f);
}

// ---------------- host launcher ----------------
extern "C" void kernel_launch(void* const* d_in, const int* in_sizes, int n_in,
                              void* d_out, int out_size)
{
    const float* pxyz = (const float*)d_in[0];
    const float* feat = (const float*)d_in[1];
    const int*   ind  = (const int*)d_in[2];
    const float* w1 = (const float*)d_in[3];  const float* b1 = (const float*)d_in[4];
    const float* g1 = (const float*)d_in[5];  const float* be1 = (const float*)d_in[6];
    const float* w2 = (const float*)d_in[7];  const float* b2 = (const float*)d_in[8];
    const float* g2 = (const float*)d_in[9];  const float* be2 = (const float*)d_in[10];
    const float* w3 = (const float*)d_in[11]; const float* b3 = (const float*)d_in[12];
    const float* g3 = (const float*)d_in[13]; const float* be3 = (const float*)d_in[14];

    float* out  = (float*)d_out;
    float* nxyz = out;
    float* fout = out + Bb * Mq * 3;

    float *pY1, *pY2, *pFT;
    __half* pWh;
    cudaGetSymbolAddress((void**)&pY1, g_Y1);
    cudaGetSymbolAddress((void**)&pY2, g_Y2);
    cudaGetSymbolAddress((void**)&pFT, g_featT);
    cudaGetSymbolAddress((void**)&pWh, g_Whf);

    const int DSM = 4 * ABUF * 2;   // 40960 bytes (A x2 + B x2, fp16)
    cudaFuncSetAttribute(k_gemm_h<0,0>, cudaFuncAttributeMaxDynamicSharedMemorySize, DSM);
    cudaFuncSetAttribute(k_gemm_h<1,0>, cudaFuncAttributeMaxDynamicSharedMemorySize, DSM);
    cudaFuncSetAttribute(k_gemm_h<1,1>, cudaFuncAttributeMaxDynamicSharedMemorySize, DSM);

    const int W2_OFF = KCP1 * 128;
    const int W3_OFF = KCP1 * 128 + 128 * 128;

    k_newxyz<<<(Bb * Mq + 255) / 256, 256>>>(pxyz, ind, nxyz);
    k_ballquery<<<(Bb * Mq * 32) / 256, 256>>>(pxyz, nxyz);
    k_transpose<<<dim3(Np / 32, Cf / 32, Bb), dim3(32, 8)>>>(feat, pFT);

    k_packW<<<128, KCP1>>>(w1, pWh, 131, KCP1, 1);
    k_packW<<<128, 128>>>(w2, pWh + W2_OFF, 128, 128, 0);
    k_packW<<<256, 128>>>(w3, pWh + W3_OFF, 128, 128, 0);

    // layer 1: fused gather/concat, K = 160 -> 5 chunks
    k_gemm_h<0,0><<<dim3(NCTA, 1), 256, DSM>>>(pWh, b1, 5, KCP1,
                                               nullptr, pxyz, nxyz, pY1);
    k_reduce<<<128, 256>>>(g1, be1);

    // layer 2: fused BN1+ReLU, K = 128 -> 4 chunks
    k_gemm_h<1,0><<<dim3(NCTA, 1), 256, DSM>>>(pWh + W2_OFF, b2, 4, 128,
                                               pY1, nullptr, nullptr, pY2);
    k_reduce<<<128, 256>>>(g2, be2);

    // layer 3: fused BN2+ReLU, 256 out channels, max fused into epilogue (no Y3)
    k_gemm_h<1,1><<<dim3(NCTA, 2), 256, DSM>>>(pWh + W3_OFF, b3, 4, 128,
                                               pY2, nullptr, nullptr, nullptr);
    k_reduce<<<256, 256>>>(g3, be3);

    // BN3+ReLU on per-query maxima (4MB read, 4MB write)
    k_final<<<(Bb * 256 * Mq) / 256, 256>>>(fout);
}